// round 15
// baseline (speedup 1.0000x reference)
#include <cuda_runtime.h>
#include <cuda_fp16.h>
#include <cstdint>
#include <cstddef>

// ---------------------------------------------------------------- problem dims
#define N_ATOMS   20000
#define ATOM_F    256
#define EDGE_F    128
#define IN_F      640           // 2*ATOM_F + EDGE_F
#define OUT_F     256
#define E_TOTAL   640000

// ---------------------------------------------------------------- tile config
#define BM        128           // edges per CTA
#define BN        128           // out features per CTA (2 column tiles)
#define BKH       64            // fp16 per sub-chunk = 128 bytes per row
#define NCHUNK    (IN_F / BKH)  // 10 sub-chunks
#define NSTAGES_D (NCHUNK / 2)  // 5 data stages (2 sub-chunks each)
#define THREADS   256           // 8 warps, warp tile 64x32

#define SUB_BYTES   (BM * 128)              // 16384 per sub-chunk
#define STAGE_BYTES (2 * SUB_BYTES)         // 32768 (A only; B bypasses smem)
#define NSTAGE      3
#define SMEM_BYTES  (NSTAGE * STAGE_BYTES)  // 98304 -> 2 CTAs/SM

// ---------------------------------------------------------------- scratch globals
// W pre-packed into mma B-fragment order:
// uint32 index u = ((((nb*10 + c)*4 + wn)*8 + j)*32 + lane)*4 + r
//   j = ks*2 + ntp ; r: {b0,b1 of nt=2ntp, b0,b1 of nt=2ntp+1}
__device__ uint4  g_wp4[2 * NCHUNK * 4 * 8 * 32];    // 20480 uint4 = 320KB
__device__ __half g_h16[N_ATOMS * ATOM_F];           // h fp16
__device__ __half g_m16[(size_t)E_TOTAL * EDGE_F];   // m_rbf fp16
__device__ int    g_ia[E_TOTAL];                     // idnb_a as int32
__device__ int    g_ic[E_TOTAL];                     // idnb_c as int32

// ---------------------------------------------------------------- ptx helpers
__device__ __forceinline__ uint32_t smem_u32(const void* p) {
    uint32_t a;
    asm("{ .reg .u64 t; cvta.to.shared.u64 t, %1; cvt.u32.u64 %0, t; }" : "=r"(a) : "l"(p));
    return a;
}

#define CP_ASYNC16(dst, src) \
    asm volatile("cp.async.cg.shared.global [%0], [%1], 16;" :: "r"(dst), "l"(src) : "memory")
#define CP_COMMIT() asm volatile("cp.async.commit_group;" ::: "memory")
#define CP_WAIT1()  asm volatile("cp.async.wait_group 1;" ::: "memory")
#define CP_WAIT0()  asm volatile("cp.async.wait_group 0;" ::: "memory")

__device__ __forceinline__ void ldm_x4(uint32_t* r, uint32_t addr) {
    asm volatile("ldmatrix.sync.aligned.m8n8.x4.shared.b16 {%0,%1,%2,%3}, [%4];"
                 : "=r"(r[0]), "=r"(r[1]), "=r"(r[2]), "=r"(r[3]) : "r"(addr));
}

__device__ __forceinline__ void mma_f16(float* d, const uint32_t* a, const uint32_t* b) {
    asm volatile(
        "mma.sync.aligned.m16n8k16.row.col.f32.f16.f16.f32 "
        "{%0,%1,%2,%3}, {%4,%5,%6,%7}, {%8,%9}, {%0,%1,%2,%3};"
        : "+f"(d[0]), "+f"(d[1]), "+f"(d[2]), "+f"(d[3])
        : "r"(a[0]), "r"(a[1]), "r"(a[2]), "r"(a[3]), "r"(b[0]), "r"(b[1]));
}

__device__ __forceinline__ float silu_f(float x) {
    float e, r;
    asm("ex2.approx.f32 %0, %1;" : "=f"(e) : "f"(-1.4426950408889634f * x));
    asm("rcp.approx.f32 %0, %1;" : "=f"(r) : "f"(1.0f + e));
    return x * r;
}

__device__ __forceinline__ uint32_t pack_h2(float lo, float hi) {
    __half2 h = __floats2half2_rn(lo, hi);
    return *reinterpret_cast<uint32_t*>(&h);
}

// ---------------------------------------------------------------- single prep kernel
// block roles: [0,2500) indices  [2500,2820) W pack  [2820,7820) h  [7820,47820) m_rbf
#define IDX_BLOCKS 2500
#define WP_BLOCKS  320          // 81920 uint32 / 256
#define H_BLOCKS   5000
#define M_BLOCKS   40000
#define PREP_GRID  (IDX_BLOCKS + WP_BLOCKS + H_BLOCKS + M_BLOCKS)

__global__ void prep_kernel(const int* __restrict__ ra, const int* __restrict__ rc,
                            const float* __restrict__ W, const float* __restrict__ h,
                            const float* __restrict__ m) {
    int b = blockIdx.x, t = threadIdx.x;
    if (b < IDX_BLOCKS) {
        // Per-block dtype detection, sampling ONLY within the first E_TOTAL
        // 32-bit words (in-bounds for BOTH int32 and int64 layouts).
        __shared__ int sflag;
        if (t == 0) sflag = 0;
        __syncthreads();
        int i = b * 256 + t;
        int j = (i < E_TOTAL / 2) ? i : i - E_TOTAL / 2;   // j < 320000
        if (ra[2 * j + 1] != 0) sflag = 1;
        __syncthreads();
        int src = sflag ? i : 2 * i;
        g_ia[i] = ra[src];
        g_ic[i] = rc[src];
    } else if (b < IDX_BLOCKS + WP_BLOCKS) {
        // pack W into B-fragment order (RNE fp16)
        int u  = (b - IDX_BLOCKS) * 256 + t;
        int r    = u & 3;
        int u2   = u >> 2;
        int lane = u2 & 31;
        int u3   = u2 >> 5;
        int jj   = u3 & 7;
        int u4   = u3 >> 3;
        int wn   = u4 & 3;
        int u5   = u4 >> 2;
        int c    = u5 % NCHUNK;
        int nb   = u5 / NCHUNK;
        int ks   = jj >> 1;
        int ntp  = jj & 1;
        int nt   = ntp * 2 + (r >> 1);
        int kh   = r & 1;
        int n = nb * 128 + wn * 32 + nt * 8 + (lane >> 2);
        int k = c * BKH + ks * 16 + 2 * (lane & 3) + 8 * kh;
        reinterpret_cast<uint32_t*>(g_wp4)[u] =
            pack_h2(W[(size_t)k * OUT_F + n], W[(size_t)(k + 1) * OUT_F + n]);
    } else if (b < IDX_BLOCKS + WP_BLOCKS + H_BLOCKS) {
        int i4 = (b - IDX_BLOCKS - WP_BLOCKS) * 256 + t;   // float4 index
        float4 v = reinterpret_cast<const float4*>(h)[i4];
        uint2 o;
        o.x = pack_h2(v.x, v.y);
        o.y = pack_h2(v.z, v.w);
        reinterpret_cast<uint2*>(g_h16)[i4] = o;
    } else {
        size_t i8 = (size_t)(b - IDX_BLOCKS - WP_BLOCKS - H_BLOCKS) * 2048 + (size_t)t * 8;
        float4 v0 = reinterpret_cast<const float4*>(m)[i8 / 4];
        float4 v1 = reinterpret_cast<const float4*>(m)[i8 / 4 + 1];
        uint4 o;
        o.x = pack_h2(v0.x, v0.y);
        o.y = pack_h2(v0.z, v0.w);
        o.z = pack_h2(v1.x, v1.y);
        o.w = pack_h2(v1.z, v1.w);
        reinterpret_cast<uint4*>(g_m16)[i8 / 8] = o;
    }
}

// ---------------------------------------------------------------- main kernel
__global__ __launch_bounds__(THREADS, 2)
void edge_mma_kernel(float* __restrict__ out) {
    extern __shared__ char smem[];
    uint32_t sb = smem_u32(smem);
    int tid  = threadIdx.x;
    int warp = tid >> 5;
    int lane = tid & 31;
    int bx   = blockIdx.x;
    int e0   = (bx >> 1) * BM;
    int n0   = (bx & 1) * BN;

    // -------- A loader: thread pair per edge row, 4 x 16B segs per sub-chunk --------
    int arow    = tid >> 1;
    int segbase = (tid & 1) * 4;
    const __half* pa = g_h16 + (size_t)g_ia[e0 + arow] * ATOM_F;
    const __half* pc = g_h16 + (size_t)g_ic[e0 + arow] * ATOM_F;
    const __half* pm = g_m16 + (size_t)(e0 + arow) * EDGE_F;
    uint32_t sw  = (uint32_t)(arow & 7);
    uint32_t dAr = sb + (uint32_t)(arow * 128);

    // loads sub-chunk c into stage st, sub-slot (c&1)
#define LOAD_SUB(c, st)                                                         \
    do {                                                                        \
        uint32_t dA = dAr + (uint32_t)(st) * STAGE_BYTES                        \
                          + (uint32_t)((c) & 1) * SUB_BYTES;                    \
        const __half* srcA = ((c) < 4) ? pa + (c) * BKH                         \
                           : ((c) < 8) ? pc + ((c) - 4) * BKH                   \
                           : pm + ((c) - 8) * BKH;                              \
        _Pragma("unroll")                                                       \
        for (int i_ = 0; i_ < 4; ++i_) {                                        \
            int seg = segbase + i_;                                             \
            uint32_t off = ((uint32_t)seg ^ sw) << 4;                           \
            CP_ASYNC16(dA + off, srcA + seg * 8);                               \
        }                                                                       \
    } while (0)

    // -------- prologue: stages 0 and 1 (sub-chunks 0-3) --------
    LOAD_SUB(0, 0); LOAD_SUB(1, 0); CP_COMMIT();
    LOAD_SUB(2, 1); LOAD_SUB(3, 1); CP_COMMIT();

    // -------- compute setup: warp tile 64x32 --------
    int warpM = warp >> 2;       // 0..1
    int warpN = warp & 3;        // 0..3
    int lr = lane >> 2;          // 0..7
    int lc = lane & 3;           // 0..3

    // A ldmatrix base addresses (XOR-folded swizzle)
    uint32_t A0[4];
    {
        uint32_t am = (uint32_t)(lane >> 4);
#pragma unroll
        for (int mt = 0; mt < 4; ++mt) {
            int r = warpM * 64 + mt * 16 + (lane & 15);
            A0[mt] = (uint32_t)(r * 128) + ((am ^ (uint32_t)(r & 7)) << 4);
        }
    }

    // B fragment source: packed W, per (nb, c, warpN, lane); per-sub-chunk stride 1024 uint4
    const uint4* wp = g_wp4 + (((size_t)(bx & 1) * NCHUNK * 4 + warpN) * 8) * 32 + lane;

    float acc[4][4][4];
#pragma unroll
    for (int mt = 0; mt < 4; ++mt)
#pragma unroll
        for (int nt = 0; nt < 4; ++nt)
#pragma unroll
            for (int i = 0; i < 4; ++i) acc[mt][nt][i] = 0.0f;

    uint32_t bfr[4][4][2];   // [ks][nt][reg]
#define LOAD_BFR(c)                                                             \
    do {                                                                        \
        const uint4* wpc = wp + (size_t)(c) * 1024;                             \
        _Pragma("unroll")                                                       \
        for (int j_ = 0; j_ < 8; ++j_) {                                        \
            uint4 q = wpc[j_ * 32];                                             \
            int ks_ = j_ >> 1, ntb_ = (j_ & 1) * 2;                             \
            bfr[ks_][ntb_][0]     = q.x;                                        \
            bfr[ks_][ntb_][1]     = q.y;                                        \
            bfr[ks_][ntb_ + 1][0] = q.z;                                        \
            bfr[ks_][ntb_ + 1][1] = q.w;                                        \
        }                                                                       \
    } while (0)

    // process one 64-K sub-chunk resident at smem base sAs (B already in bfr)
#define PROC_SUB(sAs)                                                           \
    do {                                                                        \
        uint32_t af[3][4];                                                      \
        ldm_x4(af[0], (sAs) + A0[0]);                                           \
        ldm_x4(af[1], (sAs) + A0[1]);                                           \
        ldm_x4(af[2], (sAs) + A0[2]);                                           \
        _Pragma("unroll")                                                       \
        for (int p = 0; p < 16; ++p) {                                          \
            int ks_ = p >> 2;                                                   \
            int mt_ = p & 3;                                                    \
            int sl_ = p - (p / 3) * 3;                                          \
            _Pragma("unroll")                                                   \
            for (int nt_ = 0; nt_ < 4; ++nt_)                                   \
                mma_f16(acc[mt_][nt_], af[sl_], bfr[ks_][nt_]);                 \
            if (p < 13) {                                                       \
                int pn_ = p + 3;                                                \
                ldm_x4(af[sl_], ((sAs) + A0[pn_ & 3]) ^ ((uint32_t)(pn_ >> 2) << 5)); \
            }                                                                   \
        }                                                                       \
    } while (0)

    // -------- mainloop: 5 stages x 2 sub-chunks; ONE barrier per stage --------
#pragma unroll 1
    for (int s = 0; s < NSTAGES_D; ++s) {
        int c0 = 2 * s;
        LOAD_BFR(c0);                       // B for sub 0, issued before the wait

        if (s < NSTAGES_D - 1) CP_WAIT1(); else CP_WAIT0();
        __syncthreads();

        int sn = s + 2;
        if (sn < NSTAGES_D) {
            int st = sn - (sn / 3) * 3;
            LOAD_SUB(2 * sn, st);
            LOAD_SUB(2 * sn + 1, st);
            CP_COMMIT();
        }

        uint32_t sA = sb + (uint32_t)(s - (s / 3) * 3) * STAGE_BYTES;

        PROC_SUB(sA);                       // sub-chunk 0
        LOAD_BFR(c0 + 1);                   // B for sub 1 (no barrier: warps desync,
                                            // LDG latency covered by other warps' mma)
        PROC_SUB(sA + SUB_BYTES);           // sub-chunk 1
    }

    // -------- epilogue: silu + store --------
#pragma unroll
    for (int mt = 0; mt < 4; ++mt) {
        int r = e0 + warpM * 64 + mt * 16 + lr;
#pragma unroll
        for (int nt = 0; nt < 4; ++nt) {
            int col = n0 + warpN * 32 + nt * 8 + lc * 2;
            float2 v0, v1;
            v0.x = silu_f(acc[mt][nt][0]);
            v0.y = silu_f(acc[mt][nt][1]);
            v1.x = silu_f(acc[mt][nt][2]);
            v1.y = silu_f(acc[mt][nt][3]);
            *reinterpret_cast<float2*>(out + (size_t)r * OUT_F + col)       = v0;
            *reinterpret_cast<float2*>(out + (size_t)(r + 8) * OUT_F + col) = v1;
        }
    }
}

// ---------------------------------------------------------------- launch
extern "C" void kernel_launch(void* const* d_in, const int* in_sizes, int n_in,
                              void* d_out, int out_size) {
    const float* h     = (const float*)d_in[0];
    const float* m_rbf = (const float*)d_in[1];
    const int*   ia    = (const int*)d_in[2];     // int32 or int64, detected per-block
    const int*   ic    = (const int*)d_in[3];
    const float* W     = (const float*)d_in[4];
    float*       out   = (float*)d_out;

    prep_kernel<<<PREP_GRID, 256>>>(ia, ic, W, h, m_rbf);

    cudaFuncSetAttribute(edge_mma_kernel,
                         cudaFuncAttributeMaxDynamicSharedMemorySize, SMEM_BYTES);
    edge_mma_kernel<<<(E_TOTAL / BM) * 2, THREADS, SMEM_BYTES>>>(out);
}

// round 16
// speedup vs baseline: 1.1631x; 1.1631x over previous
#include <cuda_runtime.h>
#include <cuda_fp16.h>
#include <cstdint>
#include <cstddef>

// ---------------------------------------------------------------- problem dims
#define N_ATOMS   20000
#define ATOM_F    256
#define EDGE_F    128
#define IN_F      640
#define OUT_F     256
#define E_TOTAL   640000

#define BKH       64            // fp16 per sub-chunk (K=64)
#define NCHUNK    10            // chunks 0-3: W1, 4-7: W2, 8-9: W3
#define THREADS   256
#define N_TILES_P 157           // ceil(20000/128)
#define P_ROWS    (N_TILES_P * 128)   // 20096 (padded)

// edge kernel smem: 2 fp32 m_rbf sub-chunks, 128 rows x 256B
#define SMEM_BYTES  65536       // also = pgemm's 4 x 16KB fp16 stages

// ---------------------------------------------------------------- scratch globals
// W packed in mma B-fragment order (all 640 K as 10 chunks):
// uint32 index u = ((((nb*10 + c)*4 + wn)*8 + j)*32 + lane)*4 + r
__device__ uint4  g_wp4[2 * NCHUNK * 4 * 8 * 32];      // 320KB
__device__ __half g_h16[N_ATOMS * ATOM_F];             // h fp16
__device__ float  g_P[2 * (size_t)P_ROWS * OUT_F];     // P1|P2, fp32, padded rows
__device__ int    g_ia[E_TOTAL];
__device__ int    g_ic[E_TOTAL];

// ---------------------------------------------------------------- ptx helpers
__device__ __forceinline__ uint32_t smem_u32(const void* p) {
    uint32_t a;
    asm("{ .reg .u64 t; cvta.to.shared.u64 t, %1; cvt.u32.u64 %0, t; }" : "=r"(a) : "l"(p));
    return a;
}

#define CP_ASYNC16(dst, src) \
    asm volatile("cp.async.cg.shared.global [%0], [%1], 16;" :: "r"(dst), "l"(src) : "memory")
#define CP_COMMIT() asm volatile("cp.async.commit_group;" ::: "memory")
#define CP_WAIT1()  asm volatile("cp.async.wait_group 1;" ::: "memory")
#define CP_WAIT0()  asm volatile("cp.async.wait_group 0;" ::: "memory")

__device__ __forceinline__ void ldm_x4(uint32_t* r, uint32_t addr) {
    asm volatile("ldmatrix.sync.aligned.m8n8.x4.shared.b16 {%0,%1,%2,%3}, [%4];"
                 : "=r"(r[0]), "=r"(r[1]), "=r"(r[2]), "=r"(r[3]) : "r"(addr));
}

__device__ __forceinline__ float2 lds_f2(uint32_t a) {
    float2 v;
    asm volatile("ld.shared.v2.f32 {%0,%1}, [%2];" : "=f"(v.x), "=f"(v.y) : "r"(a));
    return v;
}

__device__ __forceinline__ void mma_f16(float* d, const uint32_t* a, const uint32_t* b) {
    asm volatile(
        "mma.sync.aligned.m16n8k16.row.col.f32.f16.f16.f32 "
        "{%0,%1,%2,%3}, {%4,%5,%6,%7}, {%8,%9}, {%0,%1,%2,%3};"
        : "+f"(d[0]), "+f"(d[1]), "+f"(d[2]), "+f"(d[3])
        : "r"(a[0]), "r"(a[1]), "r"(a[2]), "r"(a[3]), "r"(b[0]), "r"(b[1]));
}

__device__ __forceinline__ float silu_f(float x) {
    float e, r;
    asm("ex2.approx.f32 %0, %1;" : "=f"(e) : "f"(-1.4426950408889634f * x));
    asm("rcp.approx.f32 %0, %1;" : "=f"(r) : "f"(1.0f + e));
    return x * r;
}

__device__ __forceinline__ uint32_t pack_h2(float lo, float hi) {
    __half2 h = __floats2half2_rn(lo, hi);
    return *reinterpret_cast<uint32_t*>(&h);
}

// ---------------------------------------------------------------- prep kernel
// block roles: [0,2500) indices  [2500,2820) W pack  [2820,7820) h->fp16
#define IDX_BLOCKS 2500
#define WP_BLOCKS  320
#define H_BLOCKS   5000
#define PREP_GRID  (IDX_BLOCKS + WP_BLOCKS + H_BLOCKS)

__global__ void prep_kernel(const int* __restrict__ ra, const int* __restrict__ rc,
                            const float* __restrict__ W, const float* __restrict__ h) {
    int b = blockIdx.x, t = threadIdx.x;
    if (b < IDX_BLOCKS) {
        // dtype detection within first E_TOTAL 32-bit words (in-bounds both layouts)
        __shared__ int sflag;
        if (t == 0) sflag = 0;
        __syncthreads();
        int i = b * 256 + t;
        int j = (i < E_TOTAL / 2) ? i : i - E_TOTAL / 2;
        if (ra[2 * j + 1] != 0) sflag = 1;
        __syncthreads();
        int src = sflag ? i : 2 * i;
        g_ia[i] = ra[src];
        g_ic[i] = rc[src];
    } else if (b < IDX_BLOCKS + WP_BLOCKS) {
        int u  = (b - IDX_BLOCKS) * 256 + t;
        int r    = u & 3;
        int u2   = u >> 2;
        int lane = u2 & 31;
        int u3   = u2 >> 5;
        int jj   = u3 & 7;
        int u4   = u3 >> 3;
        int wn   = u4 & 3;
        int u5   = u4 >> 2;
        int c    = u5 % NCHUNK;
        int nb   = u5 / NCHUNK;
        int ks   = jj >> 1;
        int ntp  = jj & 1;
        int nt   = ntp * 2 + (r >> 1);
        int kh   = r & 1;
        int n = nb * 128 + wn * 32 + nt * 8 + (lane >> 2);
        int k = c * BKH + ks * 16 + 2 * (lane & 3) + 8 * kh;
        reinterpret_cast<uint32_t*>(g_wp4)[u] =
            pack_h2(W[(size_t)k * OUT_F + n], W[(size_t)(k + 1) * OUT_F + n]);
    } else {
        int i4 = (b - IDX_BLOCKS - WP_BLOCKS) * 256 + t;   // float4 index
        float4 v = reinterpret_cast<const float4*>(h)[i4];
        uint2 o;
        o.x = pack_h2(v.x, v.y);
        o.y = pack_h2(v.z, v.w);
        reinterpret_cast<uint2*>(g_h16)[i4] = o;
    }
}

// ---------------------------------------------------------------- shared frag macros
#define LOAD_BFR(c)                                                             \
    do {                                                                        \
        const uint4* wpc = wp + (size_t)(c) * 1024;                             \
        _Pragma("unroll")                                                       \
        for (int j_ = 0; j_ < 8; ++j_) {                                        \
            uint4 q = wpc[j_ * 32];                                             \
            int ks_ = j_ >> 1, ntb_ = (j_ & 1) * 2;                             \
            bfr[ks_][ntb_][0]     = q.x;                                        \
            bfr[ks_][ntb_][1]     = q.y;                                        \
            bfr[ks_][ntb_ + 1][0] = q.z;                                        \
            bfr[ks_][ntb_ + 1][1] = q.w;                                        \
        }                                                                       \
    } while (0)

// ---------------------------------------------------------------- P-GEMM: P = h @ {W1|W2}
__global__ __launch_bounds__(THREADS, 2)
void pgemm_kernel() {
    extern __shared__ char smem[];
    uint32_t sb = smem_u32(smem);
    int tid  = threadIdx.x;
    int warp = tid >> 5;
    int lane = tid & 31;
    int bx   = blockIdx.x;
    int tile = bx >> 2;
    int pk   = (bx >> 1) & 1;     // 0: P1 (W rows 0-255), 1: P2 (rows 256-511)
    int nb   = bx & 1;

    // A loader: contiguous h rows (clamped), fp16, 128B rows
    int arow    = tid >> 1;
    int segbase = (tid & 1) * 4;
    int atom = tile * 128 + arow;
    if (atom >= N_ATOMS) atom = N_ATOMS - 1;
    const __half* pa = g_h16 + (size_t)atom * ATOM_F;
    uint32_t sw  = (uint32_t)(arow & 7);
    uint32_t dAr = sb + (uint32_t)(arow * 128);

#pragma unroll
    for (int j = 0; j < 4; ++j) {
        uint32_t dA = dAr + (uint32_t)(j * 16384);
        const __half* src = pa + j * BKH;     // h cols j*64.. (same for P1/P2)
#pragma unroll
        for (int i_ = 0; i_ < 4; ++i_) {
            int seg = segbase + i_;
            CP_ASYNC16(dA + (((uint32_t)seg ^ sw) << 4), src + seg * 8);
        }
    }
    CP_COMMIT(); CP_WAIT0(); __syncthreads();

    int warpM = warp >> 2, warpN = warp & 3;
    int lr = lane >> 2, lc = lane & 3;

    uint32_t A0[4];
    {
        uint32_t am = (uint32_t)(lane >> 4);
#pragma unroll
        for (int mt = 0; mt < 4; ++mt) {
            int r = warpM * 64 + mt * 16 + (lane & 15);
            A0[mt] = (uint32_t)(r * 128) + ((am ^ (uint32_t)(r & 7)) << 4);
        }
    }
    const uint4* wp = g_wp4 + (((size_t)nb * NCHUNK * 4 + warpN) * 8) * 32 + lane;

    float acc[4][4][4];
#pragma unroll
    for (int mt = 0; mt < 4; ++mt)
#pragma unroll
        for (int nt = 0; nt < 4; ++nt)
#pragma unroll
            for (int i = 0; i < 4; ++i) acc[mt][nt][i] = 0.0f;

    uint32_t bfr[4][4][2];
#pragma unroll 1
    for (int j = 0; j < 4; ++j) {
        LOAD_BFR(pk * 4 + j);
        uint32_t sA = sb + (uint32_t)(j * 16384);
        uint32_t af[3][4];
        ldm_x4(af[0], sA + A0[0]);
        ldm_x4(af[1], sA + A0[1]);
        ldm_x4(af[2], sA + A0[2]);
#pragma unroll
        for (int p = 0; p < 16; ++p) {
            int ks = p >> 2, mt = p & 3, sl = p - (p / 3) * 3;
#pragma unroll
            for (int nt = 0; nt < 4; ++nt)
                mma_f16(acc[mt][nt], af[sl], bfr[ks][nt]);
            if (p < 13) {
                int pn = p + 3;
                ldm_x4(af[sl], (sA + A0[pn & 3]) ^ ((uint32_t)(pn >> 2) << 5));
            }
        }
    }

    // store fp32 P (no activation); padded rows safe
    float* Pbase = g_P + (size_t)pk * P_ROWS * OUT_F;
#pragma unroll
    for (int mt = 0; mt < 4; ++mt) {
        int r = tile * 128 + warpM * 64 + mt * 16 + lr;
        float* orow = Pbase + (size_t)r * OUT_F;
#pragma unroll
        for (int nt = 0; nt < 4; ++nt) {
            int col = nb * 128 + warpN * 32 + nt * 8 + lc * 2;
            float2 v0 = {acc[mt][nt][0], acc[mt][nt][1]};
            float2 v1 = {acc[mt][nt][2], acc[mt][nt][3]};
            *reinterpret_cast<float2*>(orow + col)               = v0;
            *reinterpret_cast<float2*>(orow + 8 * OUT_F + col)   = v1;
        }
    }
}

// ---------------------------------------------------------------- edge kernel: m@W3 + gathered P + silu
__global__ __launch_bounds__(THREADS, 2)
void edge_kernel(const float* __restrict__ m_rbf, float* __restrict__ out) {
    extern __shared__ char smem[];
    uint32_t sb = smem_u32(smem);
    int tid  = threadIdx.x;
    int warp = tid >> 5;
    int lane = tid & 31;
    int bx   = blockIdx.x;
    int e0   = (bx >> 1) * 128;
    int n0   = (bx & 1) * 128;

    // fp32 m_rbf loader: row = tid>>1, 8 x 16B segs (256B per row sub-chunk)
    int arow    = tid >> 1;
    int segbase = (tid & 1) * 8;
    const float* pm = m_rbf + (size_t)(e0 + arow) * EDGE_F;
    uint32_t sw  = (uint32_t)(arow & 7);
    uint32_t dAr = (uint32_t)(arow * 256);

#define LOAD32(c, slot)                                                         \
    do {                                                                        \
        uint32_t dA = sb + (uint32_t)(slot) * 32768u + dAr;                     \
        const float* src = pm + (c) * 64;                                       \
        _Pragma("unroll")                                                       \
        for (int i_ = 0; i_ < 8; ++i_) {                                        \
            int seg = segbase + i_;                                             \
            CP_ASYNC16(dA + (((uint32_t)seg ^ sw) << 4), src + seg * 4);        \
        }                                                                       \
    } while (0)

    LOAD32(0, 0); CP_COMMIT();
    LOAD32(1, 1); CP_COMMIT();

    int warpM = warp >> 2, warpN = warp & 3;
    int lr = lane >> 2, lc = lane & 3;
    int rA0 = warpM * 64 + lr;
    int kA  = 2 * lc;

    const uint4* wp = g_wp4 + (((size_t)(bx & 1) * NCHUNK * 4 + warpN) * 8) * 32 + lane;

    float acc[4][4][4];
#pragma unroll
    for (int mt = 0; mt < 4; ++mt)
#pragma unroll
        for (int nt = 0; nt < 4; ++nt)
#pragma unroll
            for (int i = 0; i < 4; ++i) acc[mt][nt][i] = 0.0f;

    // fp32 smem -> fp16 A fragment (canonical m16n8k16 layout)
#define A32ADDR(sAs, rr, kk) \
    ((sAs) + (uint32_t)((rr) * 256) + (((uint32_t)(((kk) >> 2) ^ ((rr) & 7))) << 4) + (uint32_t)(((kk) & 3) << 2))
#define LDA32(dst, sAs, mt_, ks_)                                               \
    do {                                                                        \
        int r_ = rA0 + (mt_) * 16;                                              \
        int k_ = kA + (ks_) * 16;                                               \
        float2 v_;                                                              \
        v_ = lds_f2(A32ADDR(sAs, r_,     k_));     (dst)[0] = pack_h2(v_.x, v_.y); \
        v_ = lds_f2(A32ADDR(sAs, r_ + 8, k_));     (dst)[1] = pack_h2(v_.x, v_.y); \
        v_ = lds_f2(A32ADDR(sAs, r_,     k_ + 8)); (dst)[2] = pack_h2(v_.x, v_.y); \
        v_ = lds_f2(A32ADDR(sAs, r_ + 8, k_ + 8)); (dst)[3] = pack_h2(v_.x, v_.y); \
    } while (0)

    uint32_t bfr[4][4][2];
#pragma unroll 1
    for (int c = 0; c < 2; ++c) {
        LOAD_BFR(8 + c);
        if (c == 0) CP_WAIT1(); else CP_WAIT0();
        __syncthreads();
        uint32_t sA = sb + (uint32_t)(c * 32768);

        uint32_t af[3][4];
        LDA32(af[0], sA, 0, 0);
        LDA32(af[1], sA, 1, 0);
        LDA32(af[2], sA, 2, 0);
#pragma unroll
        for (int p = 0; p < 16; ++p) {
            int ks = p >> 2, mt = p & 3, sl = p - (p / 3) * 3;
#pragma unroll
            for (int nt = 0; nt < 4; ++nt)
                mma_f16(acc[mt][nt], af[sl], bfr[ks][nt]);
            if (p < 13) {
                int pn = p + 3;
                LDA32(af[sl], sA, (pn & 3), (pn >> 2));
            }
        }
    }

    // epilogue: acc += P1[ia] + P2[ic], silu, store
    const float* P1 = g_P;
    const float* P2 = g_P + (size_t)P_ROWS * OUT_F;
#pragma unroll
    for (int mt = 0; mt < 4; ++mt) {
        int r = e0 + warpM * 64 + mt * 16 + lr;
        const float* p1a = P1 + (size_t)g_ia[r] * OUT_F;
        const float* p2a = P2 + (size_t)g_ic[r] * OUT_F;
        const float* p1b = P1 + (size_t)g_ia[r + 8] * OUT_F;
        const float* p2b = P2 + (size_t)g_ic[r + 8] * OUT_F;
#pragma unroll
        for (int nt = 0; nt < 4; ++nt) {
            int col = n0 + warpN * 32 + nt * 8 + lc * 2;
            float2 u1 = *reinterpret_cast<const float2*>(p1a + col);
            float2 u2 = *reinterpret_cast<const float2*>(p2a + col);
            float2 w1 = *reinterpret_cast<const float2*>(p1b + col);
            float2 w2 = *reinterpret_cast<const float2*>(p2b + col);
            float2 v0, v1;
            v0.x = silu_f(acc[mt][nt][0] + u1.x + u2.x);
            v0.y = silu_f(acc[mt][nt][1] + u1.y + u2.y);
            v1.x = silu_f(acc[mt][nt][2] + w1.x + w2.x);
            v1.y = silu_f(acc[mt][nt][3] + w1.y + w2.y);
            *reinterpret_cast<float2*>(out + (size_t)r * OUT_F + col)       = v0;
            *reinterpret_cast<float2*>(out + (size_t)(r + 8) * OUT_F + col) = v1;
        }
    }
}

// ---------------------------------------------------------------- launch
extern "C" void kernel_launch(void* const* d_in, const int* in_sizes, int n_in,
                              void* d_out, int out_size) {
    const float* h     = (const float*)d_in[0];
    const float* m_rbf = (const float*)d_in[1];
    const int*   ia    = (const int*)d_in[2];
    const int*   ic    = (const int*)d_in[3];
    const float* W     = (const float*)d_in[4];
    float*       out   = (float*)d_out;

    prep_kernel<<<PREP_GRID, 256>>>(ia, ic, W, h);

    cudaFuncSetAttribute(pgemm_kernel,
                         cudaFuncAttributeMaxDynamicSharedMemorySize, SMEM_BYTES);
    pgemm_kernel<<<N_TILES_P * 4, THREADS, SMEM_BYTES>>>();

    cudaFuncSetAttribute(edge_kernel,
                         cudaFuncAttributeMaxDynamicSharedMemorySize, SMEM_BYTES);
    edge_kernel<<<(E_TOTAL / 128) * 2, THREADS, SMEM_BYTES>>>(m_rbf, out);
}

// round 17
// speedup vs baseline: 1.6226x; 1.3951x over previous
#include <cuda_runtime.h>
#include <cuda_fp16.h>
#include <cstdint>
#include <cstddef>

// ---------------------------------------------------------------- problem dims
#define N_ATOMS   20000
#define ATOM_F    256
#define EDGE_F    128
#define IN_F      640
#define OUT_F     256
#define E_TOTAL   640000

#define BKH       64            // fp16 per chunk (K=64)
#define NCHUNK    10            // chunks 0-3: W1, 4-7: W2, 8-9: W3
#define THREADS   256
#define N_TILES_P 157           // ceil(20000/128)
#define P_ROWS    (N_TILES_P * 128)   // 20096 (padded)

#define SMEM_PG   65536         // pgemm: 4 x 16KB fp16 stages
#define SMEM_EG   32768         // edge: 2 x 16KB fp16 chunks

// ---------------------------------------------------------------- scratch globals
__device__ uint4  g_wp4[2 * NCHUNK * 4 * 8 * 32];      // W in B-frag order, 320KB
__device__ __half g_h16[N_ATOMS * ATOM_F];             // h fp16
__device__ __half g_m16[(size_t)E_TOTAL * EDGE_F];     // m_rbf fp16
__device__ float  g_P[2 * (size_t)P_ROWS * OUT_F];     // P1|P2 fp32
__device__ int    g_ia[E_TOTAL];
__device__ int    g_ic[E_TOTAL];

// ---------------------------------------------------------------- ptx helpers
__device__ __forceinline__ uint32_t smem_u32(const void* p) {
    uint32_t a;
    asm("{ .reg .u64 t; cvta.to.shared.u64 t, %1; cvt.u32.u64 %0, t; }" : "=r"(a) : "l"(p));
    return a;
}

#define CP_ASYNC16(dst, src) \
    asm volatile("cp.async.cg.shared.global [%0], [%1], 16;" :: "r"(dst), "l"(src) : "memory")
#define CP_COMMIT() asm volatile("cp.async.commit_group;" ::: "memory")
#define CP_WAIT0()  asm volatile("cp.async.wait_group 0;" ::: "memory")

__device__ __forceinline__ void ldm_x4(uint32_t* r, uint32_t addr) {
    asm volatile("ldmatrix.sync.aligned.m8n8.x4.shared.b16 {%0,%1,%2,%3}, [%4];"
                 : "=r"(r[0]), "=r"(r[1]), "=r"(r[2]), "=r"(r[3]) : "r"(addr));
}

__device__ __forceinline__ void mma_f16(float* d, const uint32_t* a, const uint32_t* b) {
    asm volatile(
        "mma.sync.aligned.m16n8k16.row.col.f32.f16.f16.f32 "
        "{%0,%1,%2,%3}, {%4,%5,%6,%7}, {%8,%9}, {%0,%1,%2,%3};"
        : "+f"(d[0]), "+f"(d[1]), "+f"(d[2]), "+f"(d[3])
        : "r"(a[0]), "r"(a[1]), "r"(a[2]), "r"(a[3]), "r"(b[0]), "r"(b[1]));
}

__device__ __forceinline__ float silu_f(float x) {
    float e, r;
    asm("ex2.approx.f32 %0, %1;" : "=f"(e) : "f"(-1.4426950408889634f * x));
    asm("rcp.approx.f32 %0, %1;" : "=f"(r) : "f"(1.0f + e));
    return x * r;
}

__device__ __forceinline__ uint32_t pack_h2(float lo, float hi) {
    __half2 h = __floats2half2_rn(lo, hi);
    return *reinterpret_cast<uint32_t*>(&h);
}

// ---------------------------------------------------------------- prep kernel
// [0,2500) indices  [2500,2820) W pack  [2820,7820) h->fp16  [7820,47820) m->fp16
#define IDX_BLOCKS 2500
#define WP_BLOCKS  320
#define H_BLOCKS   5000
#define M_BLOCKS   40000
#define PREP_GRID  (IDX_BLOCKS + WP_BLOCKS + H_BLOCKS + M_BLOCKS)

__global__ void prep_kernel(const int* __restrict__ ra, const int* __restrict__ rc,
                            const float* __restrict__ W, const float* __restrict__ h,
                            const float* __restrict__ m) {
    int b = blockIdx.x, t = threadIdx.x;
    if (b < IDX_BLOCKS) {
        __shared__ int sflag;
        if (t == 0) sflag = 0;
        __syncthreads();
        int i = b * 256 + t;
        int j = (i < E_TOTAL / 2) ? i : i - E_TOTAL / 2;
        if (ra[2 * j + 1] != 0) sflag = 1;
        __syncthreads();
        int src = sflag ? i : 2 * i;
        g_ia[i] = ra[src];
        g_ic[i] = rc[src];
    } else if (b < IDX_BLOCKS + WP_BLOCKS) {
        int u  = (b - IDX_BLOCKS) * 256 + t;
        int r    = u & 3;
        int u2   = u >> 2;
        int lane = u2 & 31;
        int u3   = u2 >> 5;
        int jj   = u3 & 7;
        int u4   = u3 >> 3;
        int wn   = u4 & 3;
        int u5   = u4 >> 2;
        int c    = u5 % NCHUNK;
        int nb   = u5 / NCHUNK;
        int ks   = jj >> 1;
        int ntp  = jj & 1;
        int nt   = ntp * 2 + (r >> 1);
        int kh   = r & 1;
        int n = nb * 128 + wn * 32 + nt * 8 + (lane >> 2);
        int k = c * BKH + ks * 16 + 2 * (lane & 3) + 8 * kh;
        reinterpret_cast<uint32_t*>(g_wp4)[u] =
            pack_h2(W[(size_t)k * OUT_F + n], W[(size_t)(k + 1) * OUT_F + n]);
    } else if (b < IDX_BLOCKS + WP_BLOCKS + H_BLOCKS) {
        int i4 = (b - IDX_BLOCKS - WP_BLOCKS) * 256 + t;
        float4 v = reinterpret_cast<const float4*>(h)[i4];
        uint2 o;
        o.x = pack_h2(v.x, v.y);
        o.y = pack_h2(v.z, v.w);
        reinterpret_cast<uint2*>(g_h16)[i4] = o;
    } else {
        size_t i8 = (size_t)(b - IDX_BLOCKS - WP_BLOCKS - H_BLOCKS) * 2048 + (size_t)t * 8;
        float4 v0 = reinterpret_cast<const float4*>(m)[i8 / 4];
        float4 v1 = reinterpret_cast<const float4*>(m)[i8 / 4 + 1];
        uint4 o;
        o.x = pack_h2(v0.x, v0.y);
        o.y = pack_h2(v0.z, v0.w);
        o.z = pack_h2(v1.x, v1.y);
        o.w = pack_h2(v1.z, v1.w);
        reinterpret_cast<uint4*>(g_m16)[i8 / 8] = o;
    }
}

// ---------------------------------------------------------------- shared frag macros
#define LOAD_BFR(c)                                                             \
    do {                                                                        \
        const uint4* wpc = wp + (size_t)(c) * 1024;                             \
        _Pragma("unroll")                                                       \
        for (int j_ = 0; j_ < 8; ++j_) {                                        \
            uint4 q = wpc[j_ * 32];                                             \
            int ks_ = j_ >> 1, ntb_ = (j_ & 1) * 2;                             \
            bfr[ks_][ntb_][0]     = q.x;                                        \
            bfr[ks_][ntb_][1]     = q.y;                                        \
            bfr[ks_][ntb_ + 1][0] = q.z;                                        \
            bfr[ks_][ntb_ + 1][1] = q.w;                                        \
        }                                                                       \
    } while (0)

#define PROC_SUB(sAs)                                                           \
    do {                                                                        \
        uint32_t af[3][4];                                                      \
        ldm_x4(af[0], (sAs) + A0[0]);                                           \
        ldm_x4(af[1], (sAs) + A0[1]);                                           \
        ldm_x4(af[2], (sAs) + A0[2]);                                           \
        _Pragma("unroll")                                                       \
        for (int p = 0; p < 16; ++p) {                                          \
            int ks_ = p >> 2, mt_ = p & 3, sl_ = p - (p / 3) * 3;               \
            _Pragma("unroll")                                                   \
            for (int nt_ = 0; nt_ < 4; ++nt_)                                   \
                mma_f16(acc[mt_][nt_], af[sl_], bfr[ks_][nt_]);                 \
            if (p < 13) {                                                       \
                int pn_ = p + 3;                                                \
                ldm_x4(af[sl_], ((sAs) + A0[pn_ & 3]) ^ ((uint32_t)(pn_ >> 2) << 5)); \
            }                                                                   \
        }                                                                       \
    } while (0)

// ---------------------------------------------------------------- P-GEMM: P = h @ {W1|W2}
__global__ __launch_bounds__(THREADS, 2)
void pgemm_kernel() {
    extern __shared__ char smem[];
    uint32_t sb = smem_u32(smem);
    int tid  = threadIdx.x;
    int warp = tid >> 5;
    int lane = tid & 31;
    int bx   = blockIdx.x;
    int tile = bx >> 2;
    int pk   = (bx >> 1) & 1;
    int nb   = bx & 1;

    int arow    = tid >> 1;
    int segbase = (tid & 1) * 4;
    int atom = tile * 128 + arow;
    if (atom >= N_ATOMS) atom = N_ATOMS - 1;
    const __half* pa = g_h16 + (size_t)atom * ATOM_F;
    uint32_t sw  = (uint32_t)(arow & 7);
    uint32_t dAr = sb + (uint32_t)(arow * 128);

#pragma unroll
    for (int j = 0; j < 4; ++j) {
        uint32_t dA = dAr + (uint32_t)(j * 16384);
        const __half* src = pa + j * BKH;
#pragma unroll
        for (int i_ = 0; i_ < 4; ++i_) {
            int seg = segbase + i_;
            CP_ASYNC16(dA + (((uint32_t)seg ^ sw) << 4), src + seg * 8);
        }
    }
    CP_COMMIT(); CP_WAIT0(); __syncthreads();

    int warpM = warp >> 2, warpN = warp & 3;
    int lr = lane >> 2, lc = lane & 3;

    uint32_t A0[4];
    {
        uint32_t am = (uint32_t)(lane >> 4);
#pragma unroll
        for (int mt = 0; mt < 4; ++mt) {
            int r = warpM * 64 + mt * 16 + (lane & 15);
            A0[mt] = (uint32_t)(r * 128) + ((am ^ (uint32_t)(r & 7)) << 4);
        }
    }
    const uint4* wp = g_wp4 + (((size_t)nb * NCHUNK * 4 + warpN) * 8) * 32 + lane;

    float acc[4][4][4];
#pragma unroll
    for (int mt = 0; mt < 4; ++mt)
#pragma unroll
        for (int nt = 0; nt < 4; ++nt)
#pragma unroll
            for (int i = 0; i < 4; ++i) acc[mt][nt][i] = 0.0f;

    uint32_t bfr[4][4][2];
#pragma unroll 1
    for (int j = 0; j < 4; ++j) {
        LOAD_BFR(pk * 4 + j);
        uint32_t sA = sb + (uint32_t)(j * 16384);
        PROC_SUB(sA);
    }

    float* Pbase = g_P + (size_t)pk * P_ROWS * OUT_F;
#pragma unroll
    for (int mt = 0; mt < 4; ++mt) {
        int r = tile * 128 + warpM * 64 + mt * 16 + lr;
        float* orow = Pbase + (size_t)r * OUT_F;
#pragma unroll
        for (int nt = 0; nt < 4; ++nt) {
            int col = nb * 128 + warpN * 32 + nt * 8 + lc * 2;
            float2 v0 = {acc[mt][nt][0], acc[mt][nt][1]};
            float2 v1 = {acc[mt][nt][2], acc[mt][nt][3]};
            *reinterpret_cast<float2*>(orow + col)             = v0;
            *reinterpret_cast<float2*>(orow + 8 * OUT_F + col) = v1;
        }
    }
}

// ---------------------------------------------------------------- edge kernel: m@W3 + gathered P + silu
__global__ __launch_bounds__(THREADS, 2)
void edge_kernel(float* __restrict__ out) {
    extern __shared__ char smem[];
    uint32_t sb = smem_u32(smem);
    int tid  = threadIdx.x;
    int warp = tid >> 5;
    int lane = tid & 31;
    int bx   = blockIdx.x;
    int e0   = (bx >> 1) * 128;
    int n0   = (bx & 1) * 128;

    // fp16 m_rbf loader: both chunks staged up front, ONE barrier total
    int arow    = tid >> 1;
    int segbase = (tid & 1) * 4;
    const __half* pm = g_m16 + (size_t)(e0 + arow) * EDGE_F;
    uint32_t sw  = (uint32_t)(arow & 7);
    uint32_t dAr = sb + (uint32_t)(arow * 128);
#pragma unroll
    for (int c = 0; c < 2; ++c) {
#pragma unroll
        for (int i_ = 0; i_ < 4; ++i_) {
            int seg = segbase + i_;
            CP_ASYNC16(dAr + (uint32_t)(c * 16384) + (((uint32_t)seg ^ sw) << 4),
                       pm + c * BKH + seg * 8);
        }
    }
    CP_COMMIT();

    int warpM = warp >> 2, warpN = warp & 3;
    int lr = lane >> 2, lc = lane & 3;

    uint32_t A0[4];
    {
        uint32_t am = (uint32_t)(lane >> 4);
#pragma unroll
        for (int mt = 0; mt < 4; ++mt) {
            int r = warpM * 64 + mt * 16 + (lane & 15);
            A0[mt] = (uint32_t)(r * 128) + ((am ^ (uint32_t)(r & 7)) << 4);
        }
    }
    const uint4* wp = g_wp4 + (((size_t)(bx & 1) * NCHUNK * 4 + warpN) * 8) * 32 + lane;

    float acc[4][4][4];
#pragma unroll
    for (int mt = 0; mt < 4; ++mt)
#pragma unroll
        for (int nt = 0; nt < 4; ++nt)
#pragma unroll
            for (int i = 0; i < 4; ++i) acc[mt][nt][i] = 0.0f;

    uint32_t bfr[4][4][2];
    LOAD_BFR(8);                  // B for chunk 0 overlaps the cp.async wait
    CP_WAIT0(); __syncthreads();

    PROC_SUB(sb);                 // chunk 0 (m cols 0-63)
    LOAD_BFR(9);                  // B for chunk 1 (covered by chunk-0 mma)
    PROC_SUB(sb + 16384u);        // chunk 1 (m cols 64-127)

    // -------- epilogue: pipelined gather-add + silu --------
    const float* P1 = g_P;
    const float* P2 = g_P + (size_t)P_ROWS * OUT_F;
    int colbase = n0 + warpN * 32 + lc * 2;

    // all 16 indices in one MLP burst (L2-resident)
    int ja[4][2], jc[4][2];
#pragma unroll
    for (int mt = 0; mt < 4; ++mt) {
        int r = e0 + warpM * 64 + mt * 16 + lr;
        ja[mt][0] = g_ia[r];     jc[mt][0] = g_ic[r];
        ja[mt][1] = g_ia[r + 8]; jc[mt][1] = g_ic[r + 8];
    }

    float2 u1[2][4], u2[2][4], w1[2][4], w2[2][4];   // [buf][nt]
#define LOADP(mt_, bf_)                                                         \
    do {                                                                        \
        const float* p1a = P1 + (size_t)ja[mt_][0] * OUT_F;                     \
        const float* p2a = P2 + (size_t)jc[mt_][0] * OUT_F;                     \
        const float* p1b = P1 + (size_t)ja[mt_][1] * OUT_F;                     \
        const float* p2b = P2 + (size_t)jc[mt_][1] * OUT_F;                     \
        _Pragma("unroll")                                                       \
        for (int nt_ = 0; nt_ < 4; ++nt_) {                                     \
            int col_ = colbase + nt_ * 8;                                       \
            u1[bf_][nt_] = *reinterpret_cast<const float2*>(p1a + col_);        \
            u2[bf_][nt_] = *reinterpret_cast<const float2*>(p2a + col_);        \
            w1[bf_][nt_] = *reinterpret_cast<const float2*>(p1b + col_);        \
            w2[bf_][nt_] = *reinterpret_cast<const float2*>(p2b + col_);        \
        }                                                                       \
    } while (0)

    LOADP(0, 0);
#pragma unroll
    for (int mt = 0; mt < 4; ++mt) {
        if (mt < 3) LOADP(mt + 1, (mt + 1) & 1);     // next group's loads in flight
        int bf = mt & 1;
        int r = e0 + warpM * 64 + mt * 16 + lr;
#pragma unroll
        for (int nt = 0; nt < 4; ++nt) {
            int col = colbase + nt * 8;
            float2 v0, v1;
            v0.x = silu_f(acc[mt][nt][0] + u1[bf][nt].x + u2[bf][nt].x);
            v0.y = silu_f(acc[mt][nt][1] + u1[bf][nt].y + u2[bf][nt].y);
            v1.x = silu_f(acc[mt][nt][2] + w1[bf][nt].x + w2[bf][nt].x);
            v1.y = silu_f(acc[mt][nt][3] + w1[bf][nt].y + w2[bf][nt].y);
            *reinterpret_cast<float2*>(out + (size_t)r * OUT_F + col)       = v0;
            *reinterpret_cast<float2*>(out + (size_t)(r + 8) * OUT_F + col) = v1;
        }
    }
}

// ---------------------------------------------------------------- launch
extern "C" void kernel_launch(void* const* d_in, const int* in_sizes, int n_in,
                              void* d_out, int out_size) {
    const float* h     = (const float*)d_in[0];
    const float* m_rbf = (const float*)d_in[1];
    const int*   ia    = (const int*)d_in[2];
    const int*   ic    = (const int*)d_in[3];
    const float* W     = (const float*)d_in[4];
    float*       out   = (float*)d_out;

    prep_kernel<<<PREP_GRID, 256>>>(ia, ic, W, h, m_rbf);

    cudaFuncSetAttribute(pgemm_kernel,
                         cudaFuncAttributeMaxDynamicSharedMemorySize, SMEM_PG);
    pgemm_kernel<<<N_TILES_P * 4, THREADS, SMEM_PG>>>();

    cudaFuncSetAttribute(edge_kernel,
                         cudaFuncAttributeMaxDynamicSharedMemorySize, SMEM_EG);
    edge_kernel<<<(E_TOTAL / 128) * 2, THREADS, SMEM_EG>>>(out);
}